// round 1
// baseline (speedup 1.0000x reference)
#include <cuda_runtime.h>

// NECTAR binning, fused single kernel.
// logits [B,4,512,512] f32, val_freqs [4,9,15] f32 -> out [B,4,512,512] f32.
//
// Per pixel:
//   probs = softmax over 4 classes; y_hard = argmax (== argmax of logits)
//   agg[c] = # of 8-neighbors (3x3 minus center, zero pad) with y_hard == c
//   bin[c] = clip(int(probs[c] / (1/15)), 0, 14)
//   cal[c] = val_freqs[c, agg[c], bin[c]];  out[c] = cal[c] / max(sum cal, guard)

#define C_NUM   4
#define H_DIM   512
#define W_DIM   512
#define N_BINS  15
#define N_NBR   9
#define TX      32
#define TY      8
#define NTHREADS 256

__global__ __launch_bounds__(NTHREADS, 8)
void nectar_binning_kernel(const float* __restrict__ logits,
                           const float* __restrict__ val_freqs,
                           float* __restrict__ out)
{
    __shared__ float         s_vf[C_NUM * N_NBR * N_BINS];     // 540 floats = 2160 B
    __shared__ unsigned char s_cls[TY + 2][TX + 2];            // argmax class per tile+halo pos
    __shared__ uchar4        s_bin[TY][TX];                    // 4 confidence bins per interior px

    const int tid = threadIdx.x;

    // load calibration table into shared
    #pragma unroll
    for (int i = tid; i < C_NUM * N_NBR * N_BINS; i += NTHREADS)
        s_vf[i] = val_freqs[i];

    const int x0 = blockIdx.x * TX;
    const int y0 = blockIdx.y * TY;
    const int b  = blockIdx.z;

    const size_t HW   = (size_t)H_DIM * W_DIM;
    const float* base = logits + (size_t)b * C_NUM * HW;

    const float bw = 1.0f / 15.0f;   // matches reference bin_width rounded to f32

    // ---- Pass A: tile + halo. argmax for all positions; softmax bins for interior. ----
    for (int i = tid; i < (TX + 2) * (TY + 2); i += NTHREADS) {
        const int lx = i % (TX + 2);
        const int ly = i / (TX + 2);
        const int gx = x0 + lx - 1;
        const int gy = y0 + ly - 1;

        unsigned char cls = 0xFF;   // out-of-image: matches no class (zero padding)
        if ((unsigned)gx < W_DIM && (unsigned)gy < H_DIM) {
            const size_t off = (size_t)gy * W_DIM + gx;
            const float l0 = __ldg(base + off);
            const float l1 = __ldg(base + off + HW);
            const float l2 = __ldg(base + off + 2 * HW);
            const float l3 = __ldg(base + off + 3 * HW);

            // argmax, first-occurrence semantics (strict >)
            float m = l0; cls = 0;
            if (l1 > m) { m = l1; cls = 1; }
            if (l2 > m) { m = l2; cls = 2; }
            if (l3 > m) { m = l3; cls = 3; }

            const bool interior = (lx >= 1) & (lx <= TX) & (ly >= 1) & (ly <= TY);
            if (interior) {
                // softmax (max-subtracted, accurate expf to keep bin boundaries aligned
                // with the reference)
                const float e0 = expf(l0 - m);
                const float e1 = expf(l1 - m);
                const float e2 = expf(l2 - m);
                const float e3 = expf(l3 - m);
                const float s   = e0 + e1 + e2 + e3;
                const float t   = (1.0f / s) / bw;   // p_i/bw == e_i * t (to ~2 ulp)
                int b0 = (int)(e0 * t); b0 = b0 > N_BINS - 1 ? N_BINS - 1 : b0;
                int b1 = (int)(e1 * t); b1 = b1 > N_BINS - 1 ? N_BINS - 1 : b1;
                int b2 = (int)(e2 * t); b2 = b2 > N_BINS - 1 ? N_BINS - 1 : b2;
                int b3 = (int)(e3 * t); b3 = b3 > N_BINS - 1 ? N_BINS - 1 : b3;
                s_bin[ly - 1][lx - 1] = make_uchar4((unsigned char)b0, (unsigned char)b1,
                                                    (unsigned char)b2, (unsigned char)b3);
            }
        }
        s_cls[ly][lx] = cls;
    }
    __syncthreads();

    // ---- Pass B: per interior pixel -> neighbor counts, table gather, normalize. ----
    const int lx = tid & (TX - 1);
    const int ly = tid >> 5;
    const int gx = x0 + lx;
    const int gy = y0 + ly;
    if (gx >= W_DIM || gy >= H_DIM) return;

    // packed per-class neighbor counts (4 bytes, max count 8 per class)
    unsigned int acc = 0;
    #pragma unroll
    for (int dy = 0; dy < 3; dy++) {
        #pragma unroll
        for (int dx = 0; dx < 3; dx++) {
            if (dx == 1 && dy == 1) continue;   // exclude center
            const unsigned int c = s_cls[ly + dy][lx + dx];
            if (c < 4u) acc += 1u << (c * 8);
        }
    }

    const uchar4 bn = s_bin[ly][lx];
    const int c0 =  acc        & 0xFF;
    const int c1 = (acc >> 8)  & 0xFF;
    const int c2 = (acc >> 16) & 0xFF;
    const int c3 = (acc >> 24) & 0xFF;

    const float f0 = s_vf[0 * (N_NBR * N_BINS) + c0 * N_BINS + bn.x];
    const float f1 = s_vf[1 * (N_NBR * N_BINS) + c1 * N_BINS + bn.y];
    const float f2 = s_vf[2 * (N_NBR * N_BINS) + c2 * N_BINS + bn.z];
    const float f3 = s_vf[3 * (N_NBR * N_BINS) + c3 * N_BINS + bn.w];

    float s = f0 + f1 + f2 + f3;
    s = (s == 0.0f) ? 1.0f : s;
    const float inv = 1.0f / s;

    const size_t off = (size_t)b * C_NUM * HW + (size_t)gy * W_DIM + gx;
    out[off]          = f0 * inv;
    out[off + HW]     = f1 * inv;
    out[off + 2 * HW] = f2 * inv;
    out[off + 3 * HW] = f3 * inv;
}

extern "C" void kernel_launch(void* const* d_in, const int* in_sizes, int n_in,
                              void* d_out, int out_size)
{
    const float* logits    = (const float*)d_in[0];
    const float* val_freqs = (const float*)d_in[1];
    float*       out       = (float*)d_out;

    const int B = in_sizes[0] / (C_NUM * H_DIM * W_DIM);   // 16

    dim3 grid(W_DIM / TX, H_DIM / TY, B);   // 16 x 64 x 16
    dim3 block(NTHREADS);
    nectar_binning_kernel<<<grid, block>>>(logits, val_freqs, out);
}

// round 2
// speedup vs baseline: 1.2699x; 1.2699x over previous
#include <cuda_runtime.h>

// NECTAR binning, fused, 4 pixels/thread vectorized.
// logits [16,4,512,512] f32, val_freqs [4,9,15] f32 -> out [16,4,512,512] f32.

#define H_DIM   512
#define W_DIM   512
#define N_BINS  15
#define HW      (H_DIM * W_DIM)          // 262144
#define TXPX    128                      // tile width in pixels
#define TY      8                        // tile height
#define NTH     256                      // threads (32 chunks x 8 rows)

// shared class-contribution map: rows 0..9 (tile rows -1..8), cols: index 4+lx
// for interior lx in [0,127]; left halo at 3, right halo at 132. Only 3..132 read.
#define CNT_W   140

__global__ __launch_bounds__(NTH, 4)
void nectar_binning_kernel(const float* __restrict__ logits,
                           const float* __restrict__ val_freqs,
                           float* __restrict__ out)
{
    __shared__ float s_vf[540];                                  // 4*9*15
    __shared__ __align__(16) unsigned int s_cnt[TY + 2][CNT_W];  // contribution words
    __shared__ uint4 s_bin[TY][32];                              // packed bins, 4 px/entry

    const int tid = threadIdx.x;

    for (int i = tid; i < 540; i += NTH) s_vf[i] = val_freqs[i];

    const int x0 = blockIdx.x * TXPX;
    const int y0 = blockIdx.y * TY;
    const unsigned int boff = blockIdx.z * 4u * HW;
    const float bw = 1.0f / 15.0f;

    // ---- Pass A (vector): 10 rows x 32 chunks of 4 px. argmax->contribution
    //      for all rows; softmax bins for interior rows 1..8. ----
    #pragma unroll
    for (int t = tid; t < 320; t += NTH) {
        const int row = t >> 5;          // 0..9
        const int c   = t & 31;          // chunk
        const int gy  = y0 + row - 1;
        unsigned int w[4] = {0u, 0u, 0u, 0u};
        const bool valid = ((unsigned)gy < (unsigned)H_DIM);
        if (valid) {
            const unsigned int off = boff + (unsigned)gy * W_DIM + (unsigned)(x0 + 4 * c);
            const float4 A = *(const float4*)(logits + off);
            const float4 Bv = *(const float4*)(logits + off + HW);
            const float4 Cv = *(const float4*)(logits + off + 2 * HW);
            const float4 Dv = *(const float4*)(logits + off + 3 * HW);
            const float p0[4] = {A.x, A.y, A.z, A.w};
            const float p1[4] = {Bv.x, Bv.y, Bv.z, Bv.w};
            const float p2[4] = {Cv.x, Cv.y, Cv.z, Cv.w};
            const float p3[4] = {Dv.x, Dv.y, Dv.z, Dv.w};

            unsigned int bins[4];
            const bool interior = (row >= 1) && (row <= TY);
            #pragma unroll
            for (int j = 0; j < 4; j++) {
                const float l0 = p0[j], l1 = p1[j], l2 = p2[j], l3 = p3[j];
                float m = l0; int k = 0;
                if (l1 > m) { m = l1; k = 1; }
                if (l2 > m) { m = l2; k = 2; }
                if (l3 > m) { m = l3; k = 3; }
                w[j] = 1u << (k * 8);
                if (interior) {
                    const float e0 = expf(l0 - m);
                    const float e1 = expf(l1 - m);
                    const float e2 = expf(l2 - m);
                    const float e3 = expf(l3 - m);
                    const float s  = e0 + e1 + e2 + e3;
                    const float tt = (1.0f / s) / bw;
                    int b0 = (int)(e0 * tt); b0 = b0 > 14 ? 14 : b0;
                    int b1 = (int)(e1 * tt); b1 = b1 > 14 ? 14 : b1;
                    int b2 = (int)(e2 * tt); b2 = b2 > 14 ? 14 : b2;
                    int b3 = (int)(e3 * tt); b3 = b3 > 14 ? 14 : b3;
                    bins[j] = (unsigned)b0 | ((unsigned)b1 << 8) |
                              ((unsigned)b2 << 16) | ((unsigned)b3 << 24);
                }
            }
            if (interior)
                s_bin[row - 1][c] = make_uint4(bins[0], bins[1], bins[2], bins[3]);
        }
        *(uint4*)&s_cnt[row][4 + 4 * c] = make_uint4(w[0], w[1], w[2], w[3]);
    }

    // ---- Pass A (edges): 10 rows x {left,right} halo columns. ----
    if (tid < 20) {
        const int r    = tid >> 1;
        const int side = tid & 1;
        const int gy   = y0 + r - 1;
        const int gx   = side ? (x0 + TXPX) : (x0 - 1);
        unsigned int w = 0u;
        if ((unsigned)gy < (unsigned)H_DIM && (unsigned)gx < (unsigned)W_DIM) {
            const unsigned int off = boff + (unsigned)gy * W_DIM + (unsigned)gx;
            const float l0 = logits[off];
            const float l1 = logits[off + HW];
            const float l2 = logits[off + 2 * HW];
            const float l3 = logits[off + 3 * HW];
            float m = l0; int k = 0;
            if (l1 > m) { m = l1; k = 1; }
            if (l2 > m) { m = l2; k = 2; }
            if (l3 > m) { m = l3; k = 3; }
            w = 1u << (k * 8);
        }
        s_cnt[r][side ? 132 : 3] = w;
    }
    __syncthreads();

    // ---- Pass B: 4 px/thread neighbor sums via sliding window, gather, norm. ----
    const int c  = tid & 31;
    const int ly = tid >> 5;
    const int bi = 3 + 4 * c;

    unsigned int ut[6], um[6], ub[6];
    #pragma unroll
    for (int k = 0; k < 6; k++) {
        ut[k] = s_cnt[ly][bi + k];
        um[k] = s_cnt[ly + 1][bi + k];
        ub[k] = s_cnt[ly + 2][bi + k];
    }
    // top/bottom: 3-wide windows; middle: skip center
    unsigned int T[4], Bt[4], M[4];
    T[0] = ut[0] + ut[1] + ut[2];
    T[1] = T[0] - ut[0] + ut[3];
    T[2] = T[1] - ut[1] + ut[4];
    T[3] = T[2] - ut[2] + ut[5];
    Bt[0] = ub[0] + ub[1] + ub[2];
    Bt[1] = Bt[0] - ub[0] + ub[3];
    Bt[2] = Bt[1] - ub[1] + ub[4];
    Bt[3] = Bt[2] - ub[2] + ub[5];
    M[0] = um[0] + um[2];
    M[1] = um[1] + um[3];
    M[2] = um[2] + um[4];
    M[3] = um[3] + um[5];

    const uint4 bnv = s_bin[ly][c];
    const unsigned int bnarr[4] = {bnv.x, bnv.y, bnv.z, bnv.w};

    float o0[4], o1[4], o2[4], o3[4];
    #pragma unroll
    for (int j = 0; j < 4; j++) {
        const unsigned int acc = T[j] + M[j] + Bt[j];
        const unsigned int bn  = bnarr[j];
        const int c0 =  acc         & 0xFF;
        const int c1 = (acc >> 8)   & 0xFF;
        const int c2 = (acc >> 16)  & 0xFF;
        const int c3 = (acc >> 24)  & 0xFF;
        const int b0 =  bn          & 0xFF;
        const int b1 = (bn >> 8)    & 0xFF;
        const int b2 = (bn >> 16)   & 0xFF;
        const int b3 = (bn >> 24)   & 0xFF;

        const float f0 = s_vf[          c0 * N_BINS + b0];
        const float f1 = s_vf[135     + c1 * N_BINS + b1];
        const float f2 = s_vf[2 * 135 + c2 * N_BINS + b2];
        const float f3 = s_vf[3 * 135 + c3 * N_BINS + b3];

        float s = f0 + f1 + f2 + f3;
        s = (s == 0.0f) ? 1.0f : s;
        const float inv = 1.0f / s;
        o0[j] = f0 * inv; o1[j] = f1 * inv; o2[j] = f2 * inv; o3[j] = f3 * inv;
    }

    const int gy = y0 + ly;
    const unsigned int obase = boff + (unsigned)gy * W_DIM + (unsigned)(x0 + 4 * c);
    *(float4*)(out + obase)          = make_float4(o0[0], o0[1], o0[2], o0[3]);
    *(float4*)(out + obase + HW)     = make_float4(o1[0], o1[1], o1[2], o1[3]);
    *(float4*)(out + obase + 2 * HW) = make_float4(o2[0], o2[1], o2[2], o2[3]);
    *(float4*)(out + obase + 3 * HW) = make_float4(o3[0], o3[1], o3[2], o3[3]);
}

extern "C" void kernel_launch(void* const* d_in, const int* in_sizes, int n_in,
                              void* d_out, int out_size)
{
    const float* logits    = (const float*)d_in[0];
    const float* val_freqs = (const float*)d_in[1];
    float*       out       = (float*)d_out;

    const int B = in_sizes[0] / (4 * HW);   // 16

    dim3 grid(W_DIM / TXPX, H_DIM / TY, B); // 4 x 64 x 16
    nectar_binning_kernel<<<grid, NTH>>>(logits, val_freqs, out);
}

// round 4
// speedup vs baseline: 1.2991x; 1.0230x over previous
#include <cuda_runtime.h>

// NECTAR binning, fused, 4 px/thread, balanced 10-warp layout, guarded fast exp.
// logits [16,4,512,512] f32, val_freqs [4,9,15] f32 -> out [16,4,512,512] f32.

#define H_DIM   512
#define W_DIM   512
#define N_BINS  15
#define HW      (H_DIM * W_DIM)
#define TXPX    128                      // tile width (pixels)
#define TY      8                        // interior tile height
#define NTH     320                      // 10 warps: one per halo-inclusive row

#define CNT_W   140                      // cols: 3 = left halo, 4+lx interior, 132 = right halo

__global__ __launch_bounds__(NTH, 4)
void nectar_binning_kernel(const float* __restrict__ logits,
                           const float* __restrict__ val_freqs,
                           float* __restrict__ out)
{
    __shared__ float s_vf[540];
    __shared__ __align__(16) unsigned int s_cnt[TY + 2][CNT_W];
    __shared__ uint4 s_bin[TY][32];

    const int tid  = threadIdx.x;
    const int row  = tid >> 5;           // 0..9 (halo-inclusive row)
    const int lane = tid & 31;           // chunk of 4 px

    for (int i = tid; i < 540; i += NTH) s_vf[i] = val_freqs[i];

    const int x0 = blockIdx.x * TXPX;
    const int y0 = blockIdx.y * TY;
    const unsigned int boff = blockIdx.z * 4u * HW;
    const float bw = 1.0f / 15.0f;

    // ---- Pass A: one vector job per thread (row, chunk). ----
    {
        const int gy = y0 + row - 1;
        unsigned int w[4] = {0u, 0u, 0u, 0u};
        if ((unsigned)gy < (unsigned)H_DIM) {
            const unsigned int off = boff + (unsigned)gy * W_DIM + (unsigned)(x0 + 4 * lane);
            const float4 A  = *(const float4*)(logits + off);
            const float4 Bv = *(const float4*)(logits + off + HW);
            const float4 Cv = *(const float4*)(logits + off + 2 * HW);
            const float4 Dv = *(const float4*)(logits + off + 3 * HW);
            const float p0[4] = {A.x, A.y, A.z, A.w};
            const float p1[4] = {Bv.x, Bv.y, Bv.z, Bv.w};
            const float p2[4] = {Cv.x, Cv.y, Cv.z, Cv.w};
            const float p3[4] = {Dv.x, Dv.y, Dv.z, Dv.w};

            const bool interior = (row >= 1) && (row <= TY);
            unsigned int bins[4];
            #pragma unroll
            for (int j = 0; j < 4; j++) {
                const float l0 = p0[j], l1 = p1[j], l2 = p2[j], l3 = p3[j];
                float m = l0; int k = 0;
                if (l1 > m) { m = l1; k = 1; }
                if (l2 > m) { m = l2; k = 2; }
                if (l3 > m) { m = l3; k = 3; }
                w[j] = 1u << (k * 8);
                if (interior) {
                    // fast path: __expf + boundary guard
                    const float e0 = __expf(l0 - m);
                    const float e1 = __expf(l1 - m);
                    const float e2 = __expf(l2 - m);
                    const float e3 = __expf(l3 - m);
                    const float s  = e0 + e1 + e2 + e3;
                    const float tt = (1.0f / s) / bw;
                    const float u0 = e0 * tt, u1 = e1 * tt, u2 = e2 * tt, u3 = e3 * tt;
                    int b0 = (int)u0, b1 = (int)u1, b2 = (int)u2, b3 = (int)u3;

                    const float g = 2e-3f;
                    const bool risky =
                        (fabsf(u0 - rintf(u0)) < g) | (fabsf(u1 - rintf(u1)) < g) |
                        (fabsf(u2 - rintf(u2)) < g) | (fabsf(u3 - rintf(u3)) < g);
                    if (risky) {
                        // exact path (matches reference bin boundaries)
                        const float a0 = expf(l0 - m);
                        const float a1 = expf(l1 - m);
                        const float a2 = expf(l2 - m);
                        const float a3 = expf(l3 - m);
                        const float as = a0 + a1 + a2 + a3;
                        const float at = (1.0f / as) / bw;
                        b0 = (int)(a0 * at);
                        b1 = (int)(a1 * at);
                        b2 = (int)(a2 * at);
                        b3 = (int)(a3 * at);
                    }
                    b0 = b0 > 14 ? 14 : b0;
                    b1 = b1 > 14 ? 14 : b1;
                    b2 = b2 > 14 ? 14 : b2;
                    b3 = b3 > 14 ? 14 : b3;
                    bins[j] = (unsigned)b0 | ((unsigned)b1 << 8) |
                              ((unsigned)b2 << 16) | ((unsigned)b3 << 24);
                }
            }
            if (interior)
                s_bin[row - 1][lane] = make_uint4(bins[0], bins[1], bins[2], bins[3]);
        }
        *(uint4*)&s_cnt[row][4 + 4 * lane] = make_uint4(w[0], w[1], w[2], w[3]);
    }

    // ---- Edge halo columns: warp 9 lanes 0..19 (light warp). ----
    if (row == 9 && lane < 20) {
        const int r    = lane >> 1;       // 0..9
        const int side = lane & 1;
        const int gy   = y0 + r - 1;
        const int gx   = side ? (x0 + TXPX) : (x0 - 1);
        unsigned int w = 0u;
        if ((unsigned)gy < (unsigned)H_DIM && (unsigned)gx < (unsigned)W_DIM) {
            const unsigned int off = boff + (unsigned)gy * W_DIM + (unsigned)gx;
            const float l0 = __ldg(logits + off);
            const float l1 = __ldg(logits + off + HW);
            const float l2 = __ldg(logits + off + 2 * HW);
            const float l3 = __ldg(logits + off + 3 * HW);
            float m = l0; int k = 0;
            if (l1 > m) { m = l1; k = 1; }
            if (l2 > m) { m = l2; k = 2; }
            if (l3 > m) { m = l3; k = 3; }
            w = 1u << (k * 8);
        }
        s_cnt[r][side ? 132 : 3] = w;
    }
    __syncthreads();

    // ---- Pass B: warps 0..7 produce output rows; window sums on packed bytes. ----
    if (tid >= 256) return;
    const int c  = lane;
    const int ly = row;                   // 0..7
    const int bi = 3 + 4 * c;

    unsigned int ut[6], um[6], ub[6];
    #pragma unroll
    for (int k = 0; k < 6; k++) {
        ut[k] = s_cnt[ly][bi + k];
        um[k] = s_cnt[ly + 1][bi + k];
        ub[k] = s_cnt[ly + 2][bi + k];
    }
    unsigned int T[4], Bt[4], M[4];
    T[0] = ut[0] + ut[1] + ut[2];
    T[1] = T[0] - ut[0] + ut[3];
    T[2] = T[1] - ut[1] + ut[4];
    T[3] = T[2] - ut[2] + ut[5];
    Bt[0] = ub[0] + ub[1] + ub[2];
    Bt[1] = Bt[0] - ub[0] + ub[3];
    Bt[2] = Bt[1] - ub[1] + ub[4];
    Bt[3] = Bt[2] - ub[2] + ub[5];
    M[0] = um[0] + um[2];
    M[1] = um[1] + um[3];
    M[2] = um[2] + um[4];
    M[3] = um[3] + um[5];

    const uint4 bnv = s_bin[ly][c];
    const unsigned int bnarr[4] = {bnv.x, bnv.y, bnv.z, bnv.w};

    float o0[4], o1[4], o2[4], o3[4];
    #pragma unroll
    for (int j = 0; j < 4; j++) {
        const unsigned int acc = T[j] + M[j] + Bt[j];
        const unsigned int bn  = bnarr[j];
        const float f0 = s_vf[          (acc         & 0xFF) * N_BINS + ( bn         & 0xFF)];
        const float f1 = s_vf[135     + ((acc >> 8)  & 0xFF) * N_BINS + ((bn >> 8)   & 0xFF)];
        const float f2 = s_vf[2 * 135 + ((acc >> 16) & 0xFF) * N_BINS + ((bn >> 16)  & 0xFF)];
        const float f3 = s_vf[3 * 135 + ((acc >> 24) & 0xFF) * N_BINS + ((bn >> 24)  & 0xFF)];

        float s = f0 + f1 + f2 + f3;
        s = (s == 0.0f) ? 1.0f : s;
        const float inv = 1.0f / s;
        o0[j] = f0 * inv; o1[j] = f1 * inv; o2[j] = f2 * inv; o3[j] = f3 * inv;
    }

    const int gy = y0 + ly;
    const unsigned int obase = boff + (unsigned)gy * W_DIM + (unsigned)(x0 + 4 * c);
    *(float4*)(out + obase)          = make_float4(o0[0], o0[1], o0[2], o0[3]);
    *(float4*)(out + obase + HW)     = make_float4(o1[0], o1[1], o1[2], o1[3]);
    *(float4*)(out + obase + 2 * HW) = make_float4(o2[0], o2[1], o2[2], o2[3]);
    *(float4*)(out + obase + 3 * HW) = make_float4(o3[0], o3[1], o3[2], o3[3]);
}

extern "C" void kernel_launch(void* const* d_in, const int* in_sizes, int n_in,
                              void* d_out, int out_size)
{
    const float* logits    = (const float*)d_in[0];
    const float* val_freqs = (const float*)d_in[1];
    float*       out       = (float*)d_out;

    const int B = in_sizes[0] / (4 * HW);   // 16

    dim3 grid(W_DIM / TXPX, H_DIM / TY, B); // 4 x 64 x 16
    nectar_binning_kernel<<<grid, NTH>>>(logits, val_freqs, out);
}

// round 5
// speedup vs baseline: 1.3688x; 1.0537x over previous
#include <cuda_runtime.h>

// NECTAR binning — warp-private streaming tiles, no barriers, no cnt/bin smem.
// logits [16,4,512,512] f32, val_freqs [4,9,15] f32 -> out [16,4,512,512] f32.
// One warp owns a 128x8 band; lane owns a 4-wide column strip; rows streamed
// -1..8 with register-resident window state; horizontal halo via shuffles.

#define H_DIM   512
#define W_DIM   512
#define HW      (H_DIM * W_DIM)
#define WPB     8            // warps per block
#define NTH     (32 * WPB)

__global__ __launch_bounds__(NTH, 4)
void nectar_binning_kernel(const float* __restrict__ logits,
                           const float* __restrict__ val_freqs,
                           float* __restrict__ out)
{
    __shared__ float s_vf[540];
    const int tid  = threadIdx.x;
    const int lane = tid & 31;
    const int wrp  = tid >> 5;

    for (int i = tid; i < 540; i += NTH) s_vf[i] = val_freqs[i];
    __syncthreads();

    const int x0    = blockIdx.x * 128;
    const int ybase = (blockIdx.y * WPB + wrp) * 8;
    const unsigned int boff = blockIdx.z * 4u * HW;
    const float bw = 1.0f / 15.0f;

    const float* pbase = logits + boff + (unsigned)x0 + 4u * (unsigned)lane;
    float*       obase = out    + boff + (unsigned)x0 + 4u * (unsigned)lane;

    const bool edgeLane = (lane == 0) | (lane == 31);
    const bool haloColOk = (lane == 0) ? (x0 > 0) : (x0 + 128 < W_DIM);
    const int  haloDx    = (lane == 0) ? -1 : 4;

    // streaming state
    unsigned int S[4];        // W3(row q-1) + M(row q), for next emit
    unsigned int W3p[4];      // W3 of previous row
    unsigned int binsp[4];    // packed bins of previous row

    #pragma unroll 1
    for (int r = -1; r <= 8; ++r) {
        const int gy = ybase + r;
        const bool vrow = ((unsigned)gy < (unsigned)H_DIM);

        unsigned int cw[4]   = {0u, 0u, 0u, 0u};
        unsigned int binw[4] = {0u, 0u, 0u, 0u};

        if (vrow) {
            const float* pr = pbase + (unsigned)gy * W_DIM;
            const float4 A  = *(const float4*)(pr);
            const float4 Bv = *(const float4*)(pr + HW);
            const float4 Cv = *(const float4*)(pr + 2 * HW);
            const float4 Dv = *(const float4*)(pr + 3 * HW);
            const float p0[4] = {A.x, A.y, A.z, A.w};
            const float p1[4] = {Bv.x, Bv.y, Bv.z, Bv.w};
            const float p2[4] = {Cv.x, Cv.y, Cv.z, Cv.w};
            const float p3[4] = {Dv.x, Dv.y, Dv.z, Dv.w};

            const bool interior = (r >= 0) & (r < 8);
            #pragma unroll
            for (int j = 0; j < 4; j++) {
                const float l0 = p0[j], l1 = p1[j], l2 = p2[j], l3 = p3[j];
                float m = l0; unsigned int w = 1u;
                if (l1 > m) { m = l1; w = 1u << 8;  }
                if (l2 > m) { m = l2; w = 1u << 16; }
                if (l3 > m) { m = l3; w = 1u << 24; }
                cw[j] = w;
                if (interior) {
                    // fast path
                    const float e0 = __expf(l0 - m);
                    const float e1 = __expf(l1 - m);
                    const float e2 = __expf(l2 - m);
                    const float e3 = __expf(l3 - m);
                    const float s  = e0 + e1 + e2 + e3;
                    const float tt = __fdividef(1.0f, s * bw);
                    const float u0 = e0 * tt, u1 = e1 * tt, u2 = e2 * tt, u3 = e3 * tt;
                    int b0 = (int)u0, b1 = (int)u1, b2 = (int)u2, b3 = (int)u3;

                    const float g = 2e-4f;   // >> fast-path error bound ~4.5e-5
                    const bool risky =
                        (fabsf(u0 - rintf(u0)) < g) | (fabsf(u1 - rintf(u1)) < g) |
                        (fabsf(u2 - rintf(u2)) < g) | (fabsf(u3 - rintf(u3)) < g);
                    if (risky) {
                        // exact path: identical to the rel_err==0 validated formula
                        const float a0 = expf(l0 - m);
                        const float a1 = expf(l1 - m);
                        const float a2 = expf(l2 - m);
                        const float a3 = expf(l3 - m);
                        const float as = a0 + a1 + a2 + a3;
                        const float at = (1.0f / as) / bw;
                        b0 = (int)(a0 * at);
                        b1 = (int)(a1 * at);
                        b2 = (int)(a2 * at);
                        b3 = (int)(a3 * at);
                    }
                    b0 = b0 > 14 ? 14 : b0;
                    b1 = b1 > 14 ? 14 : b1;
                    b2 = b2 > 14 ? 14 : b2;
                    b3 = b3 > 14 ? 14 : b3;
                    binw[j] = (unsigned)b0 | ((unsigned)b1 << 8) |
                              ((unsigned)b2 << 16) | ((unsigned)b3 << 24);
                }
            }
        }

        // block-edge halo columns (lanes 0 and 31 only)
        unsigned int hw_ = 0u;
        if (edgeLane & vrow & haloColOk) {
            const float* hp = pbase + (unsigned)gy * W_DIM + haloDx;
            const float l0 = __ldg(hp);
            const float l1 = __ldg(hp + HW);
            const float l2 = __ldg(hp + 2 * HW);
            const float l3 = __ldg(hp + 3 * HW);
            float m = l0; unsigned int w = 1u;
            if (l1 > m) { m = l1; w = 1u << 8;  }
            if (l2 > m) { m = l2; w = 1u << 16; }
            if (l3 > m) { m = l3; w = 1u << 24; }
            hw_ = w;
        }

        unsigned int prev = __shfl_up_sync(0xffffffffu, cw[3], 1);
        if (lane == 0)  prev = hw_;
        unsigned int nxt  = __shfl_down_sync(0xffffffffu, cw[0], 1);
        if (lane == 31) nxt = hw_;

        // horizontal 3-windows and skip-center windows for this row
        const unsigned int p01 = cw[0] + cw[1];
        const unsigned int p23 = cw[2] + cw[3];
        unsigned int W3[4];
        W3[0] = prev  + p01;
        W3[1] = p01   + cw[2];
        W3[2] = cw[1] + p23;
        W3[3] = p23   + nxt;

        if (r >= 1) {
            // emit output row q = r-1: acc = W3(q-1)+M(q) [=S] + W3(q+1) [=W3]
            const int qy = gy - 1;
            float o0[4], o1[4], o2[4], o3[4];
            #pragma unroll
            for (int j = 0; j < 4; j++) {
                const unsigned int acc = S[j] + W3[j];
                const unsigned int bn  = binsp[j];
                const float f0 = s_vf[      (acc         & 0xFFu) * 15 + ( bn         & 0xFFu)];
                const float f1 = s_vf[135 + ((acc >> 8)  & 0xFFu) * 15 + ((bn >> 8)   & 0xFFu)];
                const float f2 = s_vf[270 + ((acc >> 16) & 0xFFu) * 15 + ((bn >> 16)  & 0xFFu)];
                const float f3 = s_vf[405 + ((acc >> 24)        ) * 15 + ((bn >> 24)        )];
                float s = f0 + f1 + f2 + f3;
                s = (s == 0.0f) ? 1.0f : s;
                const float inv = 1.0f / s;
                o0[j] = f0 * inv; o1[j] = f1 * inv; o2[j] = f2 * inv; o3[j] = f3 * inv;
            }
            float* po = obase + (unsigned)qy * W_DIM;
            *(float4*)(po)          = make_float4(o0[0], o0[1], o0[2], o0[3]);
            *(float4*)(po + HW)     = make_float4(o1[0], o1[1], o1[2], o1[3]);
            *(float4*)(po + 2 * HW) = make_float4(o2[0], o2[1], o2[2], o2[3]);
            *(float4*)(po + 3 * HW) = make_float4(o3[0], o3[1], o3[2], o3[3]);
        }

        // shift state: S <- W3(prev row) + M(current row);  M[j] = W3[j]-cw[j]
        #pragma unroll
        for (int j = 0; j < 4; j++) {
            const unsigned int M = W3[j] - cw[j];
            S[j]   = (r >= 0) ? (W3p[j] + M) : M;   // r==-1: W3(q-1) not yet defined; q starts at 0 whose prev row is r=-1 itself
            W3p[j] = W3[j];
            binsp[j] = binw[j];
        }
    }
}

extern "C" void kernel_launch(void* const* d_in, const int* in_sizes, int n_in,
                              void* d_out, int out_size)
{
    const float* logits    = (const float*)d_in[0];
    const float* val_freqs = (const float*)d_in[1];
    float*       out       = (float*)d_out;

    const int B = in_sizes[0] / (4 * HW);       // 16

    dim3 grid(W_DIM / 128, H_DIM / (8 * WPB), B);   // 4 x 8 x 16
    nectar_binning_kernel<<<grid, NTH>>>(logits, val_freqs, out);
}

// round 6
// speedup vs baseline: 1.5100x; 1.1032x over previous
#include <cuda_runtime.h>

// NECTAR binning — warp-streaming bands, peeled halos, packed-index gather.
// logits [16,4,512,512] f32, val_freqs [4,9,15] f32 -> out [16,4,512,512] f32.

#define H_DIM 512
#define W_DIM 512
#define HW    (H_DIM * W_DIM)
#define NTH   128                    // 4 warps; warp = 128x8 band

// argmax (first-occurrence, strict >) -> packed contribution word + max value
__device__ __forceinline__ unsigned int argmax_w(float l0, float l1, float l2, float l3,
                                                 float& m) {
    m = l0; unsigned int w = 1u;
    if (l1 > m) { m = l1; w = 1u << 8;  }
    if (l2 > m) { m = l2; w = 1u << 16; }
    if (l3 > m) { m = l3; w = 1u << 24; }
    return w;
}

// contributions-only row (halo rows -1 / 8)
__device__ __forceinline__ void row_cw(const float* __restrict__ pr, unsigned int cw[4]) {
    const float4 A  = *(const float4*)(pr);
    const float4 Bv = *(const float4*)(pr + HW);
    const float4 Cv = *(const float4*)(pr + 2 * HW);
    const float4 Dv = *(const float4*)(pr + 3 * HW);
    const float p0[4] = {A.x, A.y, A.z, A.w};
    const float p1[4] = {Bv.x, Bv.y, Bv.z, Bv.w};
    const float p2[4] = {Cv.x, Cv.y, Cv.z, Cv.w};
    const float p3[4] = {Dv.x, Dv.y, Dv.z, Dv.w};
    float m;
    #pragma unroll
    for (int j = 0; j < 4; j++)
        cw[j] = argmax_w(p0[j], p1[j], p2[j], p3[j], m);
}

// full row: contributions + packed bins (guarded fast exp)
__device__ __forceinline__ void row_full(const float* __restrict__ pr,
                                         unsigned int cw[4], unsigned int binw[4]) {
    const float4 A  = *(const float4*)(pr);
    const float4 Bv = *(const float4*)(pr + HW);
    const float4 Cv = *(const float4*)(pr + 2 * HW);
    const float4 Dv = *(const float4*)(pr + 3 * HW);
    const float p0[4] = {A.x, A.y, A.z, A.w};
    const float p1[4] = {Bv.x, Bv.y, Bv.z, Bv.w};
    const float p2[4] = {Cv.x, Cv.y, Cv.z, Cv.w};
    const float p3[4] = {Dv.x, Dv.y, Dv.z, Dv.w};
    const float bw = 1.0f / 15.0f;

    #pragma unroll
    for (int j = 0; j < 4; j++) {
        const float l0 = p0[j], l1 = p1[j], l2 = p2[j], l3 = p3[j];
        float m;
        cw[j] = argmax_w(l0, l1, l2, l3, m);

        // fast path: no max-subtract (mathematically identical softmax)
        const float e0 = __expf(l0);
        const float e1 = __expf(l1);
        const float e2 = __expf(l2);
        const float e3 = __expf(l3);
        const float s  = e0 + e1 + e2 + e3;
        const float tt = __fdividef(15.0f, s);
        const float u0 = e0 * tt, u1 = e1 * tt, u2 = e2 * tt, u3 = e3 * tt;
        int b0 = (int)u0, b1 = (int)u1, b2 = (int)u2, b3 = (int)u3;

        const float g = 2e-4f;   // >> total fast-path error bound (~2e-5 abs)
        const bool risky =
            (fabsf(u0 - rintf(u0)) < g) | (fabsf(u1 - rintf(u1)) < g) |
            (fabsf(u2 - rintf(u2)) < g) | (fabsf(u3 - rintf(u3)) < g);
        if (risky) {
            // exact path: bit-validated reference formula (rel_err == 0)
            const float a0 = expf(l0 - m);
            const float a1 = expf(l1 - m);
            const float a2 = expf(l2 - m);
            const float a3 = expf(l3 - m);
            const float as = a0 + a1 + a2 + a3;
            const float at = (1.0f / as) / bw;
            b0 = (int)(a0 * at);
            b1 = (int)(a1 * at);
            b2 = (int)(a2 * at);
            b3 = (int)(a3 * at);
        }
        b0 = b0 > 14 ? 14 : b0;
        b1 = b1 > 14 ? 14 : b1;
        b2 = b2 > 14 ? 14 : b2;
        b3 = b3 > 14 ? 14 : b3;
        binw[j] = (unsigned)b0 | ((unsigned)b1 << 8) |
                  ((unsigned)b2 << 16) | ((unsigned)b3 << 24);
    }
}

// block-edge halo column word for one row (lanes 0/31 only)
__device__ __forceinline__ unsigned int halo_w(const float* __restrict__ pb,
                                               int gy, bool doit, int dx) {
    if (!doit) return 0u;
    const float* hp = pb + (unsigned)gy * W_DIM + dx;
    const float l0 = __ldg(hp);
    const float l1 = __ldg(hp + HW);
    const float l2 = __ldg(hp + 2 * HW);
    const float l3 = __ldg(hp + 3 * HW);
    float m;
    return argmax_w(l0, l1, l2, l3, m);
}

// horizontal 3-windows from lane-local cw + neighbor-lane words via shuffle
__device__ __forceinline__ void hwin(const unsigned int cw[4], unsigned int hw_,
                                     int lane, unsigned int W3[4]) {
    unsigned int prev = __shfl_up_sync(0xffffffffu, cw[3], 1);
    if (lane == 0)  prev = hw_;
    unsigned int nxt  = __shfl_down_sync(0xffffffffu, cw[0], 1);
    if (lane == 31) nxt = hw_;
    const unsigned int p01 = cw[0] + cw[1];
    const unsigned int p23 = cw[2] + cw[3];
    W3[0] = prev  + p01;
    W3[1] = p01   + cw[2];
    W3[2] = cw[1] + p23;
    W3[3] = p23   + nxt;
}

__device__ __forceinline__ void emit_row(float* __restrict__ po,
                                         const unsigned int S[4], const unsigned int W3[4],
                                         const unsigned int binsp[4],
                                         const float* __restrict__ s_vf) {
    float o0[4], o1[4], o2[4], o3[4];
    #pragma unroll
    for (int j = 0; j < 4; j++) {
        const unsigned int acc = S[j] + W3[j];
        const unsigned int idx = acc * 15u + binsp[j];   // packed per-byte: 15*cnt+bin <= 134
        const float f0 = s_vf[        ( idx         & 0xFFu)];
        const float f1 = s_vf[135u + ((idx >> 8)    & 0xFFu)];
        const float f2 = s_vf[270u + ((idx >> 16)   & 0xFFu)];
        const float f3 = s_vf[405u + ( idx >> 24          )];
        float s = f0 + f1 + f2 + f3;
        s = (s == 0.0f) ? 1.0f : s;
        const float inv = 1.0f / s;
        o0[j] = f0 * inv; o1[j] = f1 * inv; o2[j] = f2 * inv; o3[j] = f3 * inv;
    }
    *(float4*)(po)          = make_float4(o0[0], o0[1], o0[2], o0[3]);
    *(float4*)(po + HW)     = make_float4(o1[0], o1[1], o1[2], o1[3]);
    *(float4*)(po + 2 * HW) = make_float4(o2[0], o2[1], o2[2], o2[3]);
    *(float4*)(po + 3 * HW) = make_float4(o3[0], o3[1], o3[2], o3[3]);
}

__global__ __launch_bounds__(NTH, 6)
void nectar_binning_kernel(const float* __restrict__ logits,
                           const float* __restrict__ val_freqs,
                           float* __restrict__ out)
{
    __shared__ float s_vf[540];
    const int tid  = threadIdx.x;
    const int lane = tid & 31;
    const int wrp  = tid >> 5;

    for (int i = tid; i < 540; i += NTH) s_vf[i] = val_freqs[i];
    __syncthreads();

    const int x0    = blockIdx.x * 128;
    const int ybase = (blockIdx.y * 4 + wrp) * 8;
    const unsigned int boff = blockIdx.z * 4u * HW;

    const float* pb = logits + boff + (unsigned)x0 + 4u * (unsigned)lane;
    float*       ob = out    + boff + (unsigned)x0 + 4u * (unsigned)lane;

    const bool edgeLane = (lane == 0) | (lane == 31);
    const bool haloOk   = edgeLane & ((lane == 0) ? (x0 > 0) : (x0 + 128 < W_DIM));
    const int  haloDx   = (lane == 0) ? -1 : 4;

    unsigned int cw[4], binw[4], W3p[4], W3[4], S[4], binsp[4];

    // ---- row -1 (top halo, contributions only) ----
    {
        const int gy = ybase - 1;
        const bool v = (gy >= 0);
        if (v) row_cw(pb + (unsigned)gy * W_DIM, cw);
        else { cw[0] = cw[1] = cw[2] = cw[3] = 0u; }
        const unsigned int hw_ = halo_w(pb, gy, haloOk & v, haloDx);
        hwin(cw, hw_, lane, W3p);
    }

    // ---- row 0 (full) ----
    {
        row_full(pb + (unsigned)ybase * W_DIM, cw, binw);
        const unsigned int hw_ = halo_w(pb, ybase, haloOk, haloDx);
        hwin(cw, hw_, lane, W3);
        #pragma unroll
        for (int j = 0; j < 4; j++) {
            S[j]     = W3p[j] + (W3[j] - cw[j]);
            W3p[j]   = W3[j];
            binsp[j] = binw[j];
        }
    }

    // ---- rows 1..7 (full; each emits row r-1) ----
    #pragma unroll 1
    for (int r = 1; r <= 7; ++r) {
        const int gy = ybase + r;
        row_full(pb + (unsigned)gy * W_DIM, cw, binw);
        const unsigned int hw_ = halo_w(pb, gy, haloOk, haloDx);
        hwin(cw, hw_, lane, W3);
        emit_row(ob + (unsigned)(gy - 1) * W_DIM, S, W3, binsp, s_vf);
        #pragma unroll
        for (int j = 0; j < 4; j++) {
            S[j]     = W3p[j] + (W3[j] - cw[j]);
            W3p[j]   = W3[j];
            binsp[j] = binw[j];
        }
    }

    // ---- row 8 (bottom halo, contributions only) + emit row 7 ----
    {
        const int gy = ybase + 8;
        const bool v = (gy < H_DIM);
        if (v) row_cw(pb + (unsigned)gy * W_DIM, cw);
        else { cw[0] = cw[1] = cw[2] = cw[3] = 0u; }
        const unsigned int hw_ = halo_w(pb, gy, haloOk & v, haloDx);
        hwin(cw, hw_, lane, W3);
        emit_row(ob + (unsigned)(ybase + 7) * W_DIM, S, W3, binsp, s_vf);
    }
}

extern "C" void kernel_launch(void* const* d_in, const int* in_sizes, int n_in,
                              void* d_out, int out_size)
{
    const float* logits    = (const float*)d_in[0];
    const float* val_freqs = (const float*)d_in[1];
    float*       out       = (float*)d_out;

    const int B = in_sizes[0] / (4 * HW);        // 16

    dim3 grid(W_DIM / 128, 16, B);               // 4 x 16 x 16 = 1024 CTAs
    nectar_binning_kernel<<<grid, NTH>>>(logits, val_freqs, out);
}